// round 1
// baseline (speedup 1.0000x reference)
#include <cuda_runtime.h>
#include <math.h>

// ---------------- problem constants ----------------
#define BB   16
#define LL   512
#define MMCH 7
#define PP   16
#define SSTR 8
#define NPAT 64
#define DD   4096
#define HHE  32
#define KVH  8
#define HDIM 128
#define DFFN 14336
#define FCN  128
#define PREDN 96
#define BMSEQ (BB*MMCH)        // 112 sequences
#define TOK   (BMSEQ*NPAT)     // 7168 tokens
#define KFC   (NPAT*DD)        // 262144
#define KSPLIT 128
#define KCHUNK (KFC/KSPLIT)    // 2048
#define EPSV 1e-5f

// ---------------- scratch (device globals; no allocation allowed) ----------------
__device__ float g_mean[BMSEQ];
__device__ float g_std[BMSEQ];
__device__ float g_h [(size_t)TOK*DD];
__device__ float g_hn[(size_t)TOK*DD];
__device__ float g_q [(size_t)TOK*DD];
__device__ float g_k [(size_t)TOK*KVH*HDIM];
__device__ float g_v [(size_t)TOK*KVH*HDIM];
__device__ float g_o [(size_t)TOK*DD];
__device__ float g_gate[(size_t)TOK*DFFN];
__device__ float g_up  [(size_t)TOK*DFFN];
__device__ float g_zpart[(size_t)KSPLIT*BMSEQ*FCN];
__device__ float g_z[BMSEQ*FCN];

// ---------------- instance norm (RevIN stats) ----------------
__global__ void instnorm_kernel(const float* __restrict__ x) {
    __shared__ float r1[256], r2[256];
    int bm = blockIdx.x, b = bm / MMCH, m = bm % MMCH, tid = threadIdx.x;
    float s = 0.f, s2 = 0.f;
    for (int l = tid; l < LL; l += 256) {
        float v = x[((size_t)b*LL + l)*MMCH + m];
        s += v; s2 += v*v;
    }
    r1[tid] = s; r2[tid] = s2; __syncthreads();
    for (int o = 128; o; o >>= 1) {
        if (tid < o) { r1[tid] += r1[tid+o]; r2[tid] += r2[tid+o]; }
        __syncthreads();
    }
    if (tid == 0) {
        float mu  = r1[0] / (float)LL;
        float var = r2[0] / (float)LL - mu*mu;
        g_mean[bm] = mu;
        g_std[bm]  = sqrtf(var + EPSV);
    }
}

// ---------------- patch embed: h = patches @ W_in.T + b_in ----------------
__global__ void patch_kernel(const float* __restrict__ x, const float* __restrict__ Win,
                             const float* __restrict__ bin) {
    int bmn = blockIdx.x;              // token index
    int bm = bmn >> 6, n = bmn & 63;
    int b = bm / MMCH, m = bm % MMCH;
    __shared__ float patch[PP];
    int tid = threadIdx.x;
    if (tid < PP) {
        int l = n*SSTR + tid;
        if (l > LL-1) l = LL-1;        // replication pad (edge)
        patch[tid] = (x[((size_t)b*LL + l)*MMCH + m] - g_mean[bm]) / g_std[bm];
    }
    __syncthreads();
    for (int d = tid; d < DD; d += 256) {
        float acc = bin[d];
        const float* wr = Win + (size_t)d*PP;
        #pragma unroll
        for (int p = 0; p < PP; p++) acc += patch[p]*wr[p];
        g_h[(size_t)bmn*DD + d] = acc;
    }
}

// ---------------- RMSNorm ----------------
__global__ void rmsnorm_kernel(const float* __restrict__ in, const float* __restrict__ w,
                               float* __restrict__ out) {
    __shared__ float red[256];
    int row = blockIdx.x, tid = threadIdx.x;
    const float* r = in + (size_t)row*DD;
    float s = 0.f;
    for (int i = tid; i < DD; i += 256) { float v = r[i]; s += v*v; }
    red[tid] = s; __syncthreads();
    for (int o = 128; o; o >>= 1) { if (tid < o) red[tid] += red[tid+o]; __syncthreads(); }
    float scale = rsqrtf(red[0]/(float)DD + EPSV);
    float* outr = out + (size_t)row*DD;
    for (int i = tid; i < DD; i += 256) outr[i] = r[i]*scale*w[i];
}

// ---------------- classic fp32 SGEMM: C = A[M,K] @ W[N,K]^T (+res) ----------------
// All dims multiples of 128 here; K multiple of 8.
__global__ void __launch_bounds__(256, 2)
sgemm128_kernel(const float* __restrict__ A, const float* __restrict__ W,
                const float* __restrict__ res, float* __restrict__ C,
                int Nc, int K) {
    __shared__ float As[8][128];
    __shared__ float Bs[8][128];
    const int tid = threadIdx.x;
    const int tx = tid & 15, ty = tid >> 4;
    const size_t abase = (size_t)blockIdx.y * 128 * K;
    const size_t wbase = (size_t)blockIdx.x * 128 * K;
    const int lrow = tid >> 1;
    const int lcol = (tid & 1) * 4;
    float acc[8][8];
    #pragma unroll
    for (int i = 0; i < 8; i++)
        #pragma unroll
        for (int j = 0; j < 8; j++) acc[i][j] = 0.f;

    for (int k0 = 0; k0 < K; k0 += 8) {
        float4 av = *(const float4*)(A + abase + (size_t)lrow*K + k0 + lcol);
        float4 wv = *(const float4*)(W + wbase + (size_t)lrow*K + k0 + lcol);
        As[lcol+0][lrow] = av.x; As[lcol+1][lrow] = av.y;
        As[lcol+2][lrow] = av.z; As[lcol+3][lrow] = av.w;
        Bs[lcol+0][lrow] = wv.x; Bs[lcol+1][lrow] = wv.y;
        Bs[lcol+2][lrow] = wv.z; Bs[lcol+3][lrow] = wv.w;
        __syncthreads();
        #pragma unroll
        for (int k = 0; k < 8; k++) {
            float a[8], b[8];
            #pragma unroll
            for (int i = 0; i < 8; i++) a[i] = As[k][ty*8 + i];
            #pragma unroll
            for (int j = 0; j < 8; j++) b[j] = Bs[k][tx*8 + j];
            #pragma unroll
            for (int i = 0; i < 8; i++)
                #pragma unroll
                for (int j = 0; j < 8; j++)
                    acc[i][j] += a[i]*b[j];
        }
        __syncthreads();
    }
    const int rbase = blockIdx.y*128 + ty*8;
    const int cbase = blockIdx.x*128 + tx*8;
    for (int i = 0; i < 8; i++) {
        size_t off = (size_t)(rbase + i)*Nc + cbase;
        #pragma unroll
        for (int j = 0; j < 8; j++) {
            float v = acc[i][j];
            if (res) v += res[off + j];
            C[off + j] = v;
        }
    }
}

// ---------------- RoPE (in-place on q and k) ----------------
__global__ void rope_kernel() {
    int row = blockIdx.x;        // token index
    int n = row & 63;
    float* qrow = g_q + (size_t)row*DD;
    float* krow = g_k + (size_t)row*(KVH*HDIM);
    int tid = threadIdx.x;
    const int qpairs = HHE*64;   // 2048
    const int kpairs = KVH*64;   // 512
    for (int i = tid; i < qpairs + kpairs; i += 256) {
        float* base; int hh, d;
        if (i < qpairs) { base = qrow; hh = i >> 6; d = i & 63; }
        else            { int j = i - qpairs; base = krow; hh = j >> 6; d = j & 63; }
        float f = powf(500000.0f, -(float)(2*d) / 128.0f);
        float a = (float)n * f;
        float c = cosf(a), s = sinf(a);
        float t0 = base[hh*HDIM + d];
        float t1 = base[hh*HDIM + d + 64];
        base[hh*HDIM + d]      = t0*c - t1*s;
        base[hh*HDIM + d + 64] = t1*c + t0*s;
    }
}

// ---------------- attention (per bm, head); N=64, HD=128, causal ----------------
__global__ void attn_kernel() {
    extern __shared__ float sm[];
    float* Qs = sm;                    // 64*128
    float* Ks = Qs + 64*128;           // transposed [d][n] pitch 65 -> 128*65
    float* Vs = Ks + 128*65;           // 64*128
    float* Ss = Vs + 64*128;           // 64*65
    int bm = blockIdx.x, h = blockIdx.y, kvh = h >> 2;
    int tid = threadIdx.x;
    for (int i = tid; i < 64*128; i += 256) {
        int n = i >> 7, d = i & 127;
        size_t tok = (size_t)(bm*64 + n);
        Qs[i] = g_q[tok*DD + h*HDIM + d];
        Ks[d*65 + n] = g_k[tok*(KVH*HDIM) + kvh*HDIM + d];
        Vs[i] = g_v[tok*(KVH*HDIM) + kvh*HDIM + d];
    }
    __syncthreads();
    const float scale = 0.08838834764831845f;  // 1/sqrt(128)
    for (int i = tid; i < 64*64; i += 256) {
        int qi = i >> 6, ki = i & 63;
        float acc;
        if (ki <= qi) {
            acc = 0.f;
            #pragma unroll 8
            for (int d = 0; d < 128; d++) acc += Qs[qi*128 + d]*Ks[d*65 + ki];
            acc *= scale;
        } else acc = -1e9f;
        Ss[qi*65 + ki] = acc;
    }
    __syncthreads();
    if (tid < 64) {
        float mx = -1e30f;
        for (int k = 0; k < 64; k++) mx = fmaxf(mx, Ss[tid*65 + k]);
        float sum = 0.f;
        for (int k = 0; k < 64; k++) { float e = expf(Ss[tid*65 + k] - mx); Ss[tid*65 + k] = e; sum += e; }
        float inv = 1.f / sum;
        for (int k = 0; k < 64; k++) Ss[tid*65 + k] *= inv;
    }
    __syncthreads();
    for (int i = tid; i < 64*128; i += 256) {
        int qi = i >> 7, d = i & 127;
        float acc = 0.f;
        #pragma unroll 8
        for (int k = 0; k < 64; k++) acc += Ss[qi*65 + k]*Vs[k*128 + d];
        g_o[(size_t)(bm*64 + qi)*DD + h*HDIM + d] = acc;
    }
}

// ---------------- SwiGLU elementwise: gate = silu(gate)*up ----------------
__global__ void swiglu_kernel() {
    size_t idx = (size_t)blockIdx.x*256 + threadIdx.x;
    if (idx >= (size_t)TOK*DFFN) return;
    float g = g_gate[idx];
    float u = g_up[idx];
    g_gate[idx] = (g / (1.f + expf(-g))) * u;
}

// ---------------- FC head split-K partial ----------------
__global__ void fc_kernel(const float* __restrict__ Wfc) {
    int f = blockIdx.x*8 + (threadIdx.x >> 5);
    int lane = threadIdx.x & 31;
    int ks = blockIdx.y;
    size_t k0 = (size_t)ks * KCHUNK;
    const float4* wr = (const float4*)(Wfc + (size_t)f*KFC + k0);
    for (int bm = 0; bm < BMSEQ; bm++) {
        const float4* hr = (const float4*)(g_hn + (size_t)bm*KFC + k0);
        float acc = 0.f;
        for (int kk = lane; kk < KCHUNK/4; kk += 32) {
            float4 h4 = hr[kk]; float4 w4 = wr[kk];
            acc += h4.x*w4.x + h4.y*w4.y + h4.z*w4.z + h4.w*w4.w;
        }
        #pragma unroll
        for (int o = 16; o; o >>= 1) acc += __shfl_down_sync(0xffffffffu, acc, o);
        if (lane == 0) g_zpart[((size_t)ks*BMSEQ + bm)*FCN + f] = acc;
    }
}

__global__ void zreduce_kernel(const float* __restrict__ bfc) {
    int idx = blockIdx.x*256 + threadIdx.x;
    if (idx >= BMSEQ*FCN) return;
    int f = idx & 127, bm = idx >> 7;
    float acc = bfc[f];
    for (int ks = 0; ks < KSPLIT; ks++) acc += g_zpart[((size_t)ks*BMSEQ + bm)*FCN + f];
    g_z[idx] = acc;
}

// ---------------- head: leaky -> W_out -> denorm ----------------
__global__ void head_kernel(const float* __restrict__ Wout, const float* __restrict__ bout,
                            float* __restrict__ out) {
    __shared__ float zr[FCN];
    int bm = blockIdx.x, tid = threadIdx.x;
    if (tid < FCN) {
        float v = g_z[bm*FCN + tid];
        zr[tid] = v > 0.f ? v : 0.01f*v;
    }
    __syncthreads();
    if (tid < PREDN) {
        float acc = bout[tid];
        const float* wr = Wout + (size_t)tid*FCN;
        #pragma unroll 8
        for (int f = 0; f < FCN; f++) acc += zr[f]*wr[f];
        int b = bm / MMCH, m = bm % MMCH;
        out[(size_t)b*(PREDN*MMCH) + tid*MMCH + m] = acc*g_std[bm] + g_mean[bm];
    }
}

// ---------------- host driver ----------------
static void launch_gemm(const float* A, const float* W, const float* res, float* C,
                        int Mr, int Nc, int K) {
    dim3 grid(Nc/128, Mr/128);
    sgemm128_kernel<<<grid, 256>>>(A, W, res, C, Nc, K);
}

extern "C" void kernel_launch(void* const* d_in, const int* in_sizes, int n_in,
                              void* d_out, int out_size) {
    const float* x      = (const float*)d_in[0];
    const float* W_in   = (const float*)d_in[1];
    const float* b_in   = (const float*)d_in[2];
    const float* attn_w = (const float*)d_in[3];
    const float* Wq     = (const float*)d_in[4];
    const float* Wk     = (const float*)d_in[5];
    const float* Wv     = (const float*)d_in[6];
    const float* Wo     = (const float*)d_in[7];
    const float* mlp_w  = (const float*)d_in[8];
    const float* Wg     = (const float*)d_in[9];
    const float* Wu     = (const float*)d_in[10];
    const float* Wd     = (const float*)d_in[11];
    const float* fin_w  = (const float*)d_in[12];
    const float* W_fc   = (const float*)d_in[13];
    const float* b_fc   = (const float*)d_in[14];
    const float* W_out  = (const float*)d_in[15];
    const float* b_out  = (const float*)d_in[16];
    float* out = (float*)d_out;

    float *ph, *phn, *pq, *pk, *pv, *po, *pg, *pu;
    cudaGetSymbolAddress((void**)&ph,  g_h);
    cudaGetSymbolAddress((void**)&phn, g_hn);
    cudaGetSymbolAddress((void**)&pq,  g_q);
    cudaGetSymbolAddress((void**)&pk,  g_k);
    cudaGetSymbolAddress((void**)&pv,  g_v);
    cudaGetSymbolAddress((void**)&po,  g_o);
    cudaGetSymbolAddress((void**)&pg,  g_gate);
    cudaGetSymbolAddress((void**)&pu,  g_up);

    // attention shared memory: (64*128 + 128*65 + 64*128 + 64*65) floats
    const int attn_smem = (64*128 + 128*65 + 64*128 + 64*65) * (int)sizeof(float);
    cudaFuncSetAttribute(attn_kernel, cudaFuncAttributeMaxDynamicSharedMemorySize, attn_smem);

    // 1. RevIN stats
    instnorm_kernel<<<BMSEQ, 256>>>(x);
    // 2. patch embed -> h
    patch_kernel<<<TOK, 256>>>(x, W_in, b_in);
    // 3. attn RMSNorm -> hn
    rmsnorm_kernel<<<TOK, 256>>>(ph, attn_w, phn);
    // 4-6. qkv projections
    launch_gemm(phn, Wq, nullptr, pq, TOK, DD, DD);
    launch_gemm(phn, Wk, nullptr, pk, TOK, KVH*HDIM, DD);
    launch_gemm(phn, Wv, nullptr, pv, TOK, KVH*HDIM, DD);
    // 7. RoPE
    rope_kernel<<<TOK, 256>>>();
    // 8. attention
    {
        dim3 grid(BMSEQ, HHE);
        attn_kernel<<<grid, 256, attn_smem>>>();
    }
    // 9. output projection + residual: h = h + o @ Wo^T
    launch_gemm(po, Wo, ph, ph, TOK, DD, DD);
    // 10. mlp RMSNorm -> hn
    rmsnorm_kernel<<<TOK, 256>>>(ph, mlp_w, phn);
    // 11-12. gate/up
    launch_gemm(phn, Wg, nullptr, pg, TOK, DFFN, DD);
    launch_gemm(phn, Wu, nullptr, pu, TOK, DFFN, DD);
    // 13. swiglu
    {
        size_t total = (size_t)TOK*DFFN;
        int blocks = (int)((total + 255) / 256);
        swiglu_kernel<<<blocks, 256>>>();
    }
    // 14. down projection + residual: h = h + act @ Wd^T
    launch_gemm(pg, Wd, ph, ph, TOK, DD, DFFN);
    // 15. final RMSNorm -> hn
    rmsnorm_kernel<<<TOK, 256>>>(ph, fin_w, phn);
    // 16. FC head (split-K deterministic)
    {
        dim3 grid(FCN/8, KSPLIT);
        fc_kernel<<<grid, 256>>>(W_fc);
        zreduce_kernel<<<(BMSEQ*FCN + 255)/256, 256>>>(b_fc);
    }
    // 17. head + denorm
    head_kernel<<<BMSEQ, 128>>>(W_out, b_out, out);
}

// round 4
// speedup vs baseline: 3.1278x; 3.1278x over previous
#include <cuda_runtime.h>
#include <math.h>
#include <stdint.h>

// ---------------- problem constants ----------------
#define BB   16
#define LL   512
#define MMCH 7
#define PP   16
#define SSTR 8
#define NPAT 64
#define DD   4096
#define HHE  32
#define KVH  8
#define HDIM 128
#define DFFN 14336
#define FCN  128
#define PREDN 96
#define BMSEQ (BB*MMCH)        // 112
#define TOK   (BMSEQ*NPAT)     // 7168
#define KFC   (NPAT*DD)        // 262144
#define FCSPLIT 64
#define EPSV 1e-5f

// ---------------- scratch ----------------
__device__ float g_mean[BMSEQ];
__device__ float g_std[BMSEQ];
__device__ float g_h [(size_t)TOK*DD];
__device__ float g_hn[(size_t)TOK*DD];
__device__ float g_q [(size_t)TOK*DD];
__device__ float g_k [(size_t)TOK*KVH*HDIM];
__device__ float g_v [(size_t)TOK*KVH*HDIM];
__device__ float g_o [(size_t)TOK*DD];
__device__ float g_gate[(size_t)TOK*DFFN];
__device__ float g_up  [(size_t)TOK*DFFN];
__device__ float g_zpart[(size_t)FCSPLIT*128*128];
__device__ float g_z[BMSEQ*FCN];

__device__ __forceinline__ uint32_t f2tf(float f) {
    uint32_t r;
    asm("cvt.rna.tf32.f32 %0, %1;" : "=r"(r) : "f"(f));
    return r;
}
__device__ __forceinline__ void mma_tf32(float c[4], const uint32_t a[4], const uint32_t b[2]) {
    asm volatile("mma.sync.aligned.m16n8k8.row.col.f32.tf32.tf32.f32 "
        "{%0,%1,%2,%3}, {%4,%5,%6,%7}, {%8,%9}, {%0,%1,%2,%3};"
        : "+f"(c[0]), "+f"(c[1]), "+f"(c[2]), "+f"(c[3])
        : "r"(a[0]), "r"(a[1]), "r"(a[2]), "r"(a[3]), "r"(b[0]), "r"(b[1]));
}

// ---------------- mma.sync TF32 GEMM ----------------
// C[M,N] = A[M,K] @ W[N,K]^T (+epilogue). BM=BN=128, BK=32 floats.
// MODE: 0 plain, 1 add aux (residual), 2 silu(acc)*aux
#define KSTRIDE 36
#define TILEF (128*KSTRIDE)    // floats per (A or B) stage

template<int MODE>
__global__ void __launch_bounds__(256)
mma_gemm(const float* __restrict__ A, int lda,
         const float* __restrict__ W, int ldw,
         float* __restrict__ C, int ldc,
         const float* __restrict__ aux,
         int Mtiles, int Ntiles, int Mvalid, int kchunks,
         long ksA, long ksW, long ksC)
{
    extern __shared__ __align__(16) uint32_t smu[];
    const int tid = threadIdx.x;

    A += (size_t)blockIdx.y * ksA;
    W += (size_t)blockIdx.y * ksW;
    C += (size_t)blockIdx.y * ksC;

    // tile rasterization (GROUP_M=16)
    int mt, nt;
    {
        const int GM = 16;
        int perg = GM * Ntiles;
        int g = blockIdx.x / perg, rem = blockIdx.x % perg;
        int gm = Mtiles - g*GM; if (gm > GM) gm = GM;
        mt = g*GM + rem % gm;
        nt = rem / gm;
    }

    // per-thread load slots: i<4 -> A, i>=4 -> B. idx in [0,1024) each side.
    const float* gp[8];
    int so[8];
    #pragma unroll
    for (int i = 0; i < 8; i++) {
        int idx = tid + (i & 3)*256;
        int row = idx >> 3, c4 = idx & 7;
        if (i < 4) {
            int grow = mt*128 + row; if (grow >= Mvalid) grow = Mvalid-1;
            gp[i] = A + (size_t)grow*lda + c4*4;
            so[i] = row*KSTRIDE + c4*4;
        } else {
            gp[i] = W + (size_t)(nt*128 + row)*ldw + c4*4;
            so[i] = TILEF + row*KSTRIDE + c4*4;
        }
    }

    const int warp = tid >> 5, lane = tid & 31;
    const int wm = warp & 3, wn = warp >> 2;
    const int gid = lane >> 2, quad = lane & 3;

    float acc[2][8][4];
    #pragma unroll
    for (int f = 0; f < 2; f++)
        #pragma unroll
        for (int g = 0; g < 8; g++)
            #pragma unroll
            for (int j = 0; j < 4; j++) acc[f][g][j] = 0.f;

    float4 rv[8];
    #pragma unroll
    for (int i = 0; i < 8; i++) rv[i] = *(const float4*)(gp[i]);

    for (int kc = 0; kc < kchunks; kc++) {
        const int buf = kc & 1;
        uint32_t* sb = smu + buf*(2*TILEF);
        // store staged chunk (with rna->tf32 conversion)
        #pragma unroll
        for (int i = 0; i < 8; i++) {
            uint4 u;
            u.x = f2tf(rv[i].x); u.y = f2tf(rv[i].y);
            u.z = f2tf(rv[i].z); u.w = f2tf(rv[i].w);
            *(uint4*)(sb + so[i]) = u;
        }
        // issue loads for next chunk
        if (kc + 1 < kchunks) {
            #pragma unroll
            for (int i = 0; i < 8; i++) rv[i] = *(const float4*)(gp[i] + (kc+1)*32);
        }
        __syncthreads();
        // compute on buf
        const uint32_t* sA = sb;
        const uint32_t* sB = sb + TILEF;
        #pragma unroll
        for (int ks = 0; ks < 4; ks++) {
            const int kb = ks*8;
            uint32_t a[2][4];
            #pragma unroll
            for (int f = 0; f < 2; f++) {
                int r0 = wm*32 + f*16 + gid;
                a[f][0] = sA[r0*KSTRIDE + kb + quad];
                a[f][1] = sA[(r0+8)*KSTRIDE + kb + quad];
                a[f][2] = sA[r0*KSTRIDE + kb + quad + 4];
                a[f][3] = sA[(r0+8)*KSTRIDE + kb + quad + 4];
            }
            uint32_t b[8][2];
            #pragma unroll
            for (int g = 0; g < 8; g++) {
                int nr = wn*64 + g*8 + gid;
                b[g][0] = sB[nr*KSTRIDE + kb + quad];
                b[g][1] = sB[nr*KSTRIDE + kb + quad + 4];
            }
            #pragma unroll
            for (int f = 0; f < 2; f++)
                #pragma unroll
                for (int g = 0; g < 8; g++)
                    mma_tf32(acc[f][g], a[f], b[g]);
        }
        __syncthreads();
    }

    // epilogue
    #pragma unroll
    for (int f = 0; f < 2; f++) {
        int r0 = mt*128 + wm*32 + f*16 + gid;
        #pragma unroll
        for (int g = 0; g < 8; g++) {
            int col = nt*128 + wn*64 + g*8 + 2*quad;
            #pragma unroll
            for (int half = 0; half < 2; half++) {
                int row = r0 + half*8;
                if (row >= Mvalid) continue;
                float v0 = acc[f][g][half*2 + 0];
                float v1 = acc[f][g][half*2 + 1];
                size_t off = (size_t)row*ldc + col;
                if (MODE == 1) {
                    v0 += aux[off]; v1 += aux[off+1];
                } else if (MODE == 2) {
                    v0 = v0 / (1.f + __expf(-v0)) * aux[off];
                    v1 = v1 / (1.f + __expf(-v1)) * aux[off+1];
                }
                float2 o; o.x = v0; o.y = v1;
                *(float2*)(C + off) = o;
            }
        }
    }
}

// ---------------- instance norm ----------------
__global__ void instnorm_kernel(const float* __restrict__ x) {
    __shared__ float r1[256], r2[256];
    int bm = blockIdx.x, b = bm / MMCH, m = bm % MMCH, tid = threadIdx.x;
    float s = 0.f, s2 = 0.f;
    for (int l = tid; l < LL; l += 256) {
        float v = x[((size_t)b*LL + l)*MMCH + m];
        s += v; s2 += v*v;
    }
    r1[tid] = s; r2[tid] = s2; __syncthreads();
    for (int o = 128; o; o >>= 1) {
        if (tid < o) { r1[tid] += r1[tid+o]; r2[tid] += r2[tid+o]; }
        __syncthreads();
    }
    if (tid == 0) {
        float mu  = r1[0] / (float)LL;
        float var = r2[0] / (float)LL - mu*mu;
        g_mean[bm] = mu;
        g_std[bm]  = sqrtf(var + EPSV);
    }
}

// ---------------- patch embed ----------------
__global__ void patch_kernel(const float* __restrict__ x, const float* __restrict__ Win,
                             const float* __restrict__ bin) {
    int bmn = blockIdx.x;
    int bm = bmn >> 6, n = bmn & 63;
    int b = bm / MMCH, m = bm % MMCH;
    __shared__ float patch[PP];
    int tid = threadIdx.x;
    if (tid < PP) {
        int l = n*SSTR + tid;
        if (l > LL-1) l = LL-1;
        patch[tid] = (x[((size_t)b*LL + l)*MMCH + m] - g_mean[bm]) / g_std[bm];
    }
    __syncthreads();
    for (int d = tid; d < DD; d += 256) {
        float acc = bin[d];
        const float* wr = Win + (size_t)d*PP;
        #pragma unroll
        for (int p = 0; p < PP; p++) acc += patch[p]*wr[p];
        g_h[(size_t)bmn*DD + d] = acc;
    }
}

// ---------------- RMSNorm ----------------
__global__ void rmsnorm_kernel(const float* __restrict__ in, const float* __restrict__ w,
                               float* __restrict__ out) {
    __shared__ float red[256];
    int row = blockIdx.x, tid = threadIdx.x;
    const float* r = in + (size_t)row*DD;
    float s = 0.f;
    for (int i = tid; i < DD; i += 256) { float v = r[i]; s += v*v; }
    red[tid] = s; __syncthreads();
    for (int o = 128; o; o >>= 1) { if (tid < o) red[tid] += red[tid+o]; __syncthreads(); }
    float scale = rsqrtf(red[0]/(float)DD + EPSV);
    float* outr = out + (size_t)row*DD;
    for (int i = tid; i < DD; i += 256) outr[i] = r[i]*scale*w[i];
}

// ---------------- RoPE ----------------
__global__ void rope_kernel() {
    int row = blockIdx.x;
    int n = row & 63;
    float* qrow = g_q + (size_t)row*DD;
    float* krow = g_k + (size_t)row*(KVH*HDIM);
    int tid = threadIdx.x;
    const int qpairs = HHE*64;
    const int kpairs = KVH*64;
    for (int i = tid; i < qpairs + kpairs; i += 256) {
        float* base; int hh, d;
        if (i < qpairs) { base = qrow; hh = i >> 6; d = i & 63; }
        else            { int j = i - qpairs; base = krow; hh = j >> 6; d = j & 63; }
        float f = powf(500000.0f, -(float)(2*d) / 128.0f);
        float a = (float)n * f;
        float c = cosf(a), s = sinf(a);
        float t0 = base[hh*HDIM + d];
        float t1 = base[hh*HDIM + d + 64];
        base[hh*HDIM + d]      = t0*c - t1*s;
        base[hh*HDIM + d + 64] = t1*c + t0*s;
    }
}

// ---------------- attention ----------------
__global__ void attn_kernel() {
    extern __shared__ float sm[];
    float* Qs = sm;
    float* Ks = Qs + 64*128;
    float* Vs = Ks + 128*65;
    float* Ss = Vs + 64*128;
    int bm = blockIdx.x, h = blockIdx.y, kvh = h >> 2;
    int tid = threadIdx.x;
    for (int i = tid; i < 64*128; i += 256) {
        int n = i >> 7, d = i & 127;
        size_t tok = (size_t)(bm*64 + n);
        Qs[i] = g_q[tok*DD + h*HDIM + d];
        Ks[d*65 + n] = g_k[tok*(KVH*HDIM) + kvh*HDIM + d];
        Vs[i] = g_v[tok*(KVH*HDIM) + kvh*HDIM + d];
    }
    __syncthreads();
    const float scale = 0.08838834764831845f;
    for (int i = tid; i < 64*64; i += 256) {
        int qi = i >> 6, ki = i & 63;
        float acc;
        if (ki <= qi) {
            acc = 0.f;
            #pragma unroll 8
            for (int d = 0; d < 128; d++) acc += Qs[qi*128 + d]*Ks[d*65 + ki];
            acc *= scale;
        } else acc = -1e9f;
        Ss[qi*65 + ki] = acc;
    }
    __syncthreads();
    if (tid < 64) {
        float mx = -1e30f;
        for (int k = 0; k < 64; k++) mx = fmaxf(mx, Ss[tid*65 + k]);
        float sum = 0.f;
        for (int k = 0; k < 64; k++) { float e = expf(Ss[tid*65 + k] - mx); Ss[tid*65 + k] = e; sum += e; }
        float inv = 1.f / sum;
        for (int k = 0; k < 64; k++) Ss[tid*65 + k] *= inv;
    }
    __syncthreads();
    for (int i = tid; i < 64*128; i += 256) {
        int qi = i >> 7, d = i & 127;
        float acc = 0.f;
        #pragma unroll 8
        for (int k = 0; k < 64; k++) acc += Ss[qi*65 + k]*Vs[k*128 + d];
        g_o[(size_t)(bm*64 + qi)*DD + h*HDIM + d] = acc;
    }
}

// ---------------- FC reduce + head ----------------
__global__ void zreduce_kernel(const float* __restrict__ bfc) {
    int idx = blockIdx.x*256 + threadIdx.x;
    if (idx >= BMSEQ*FCN) return;
    int f = idx & 127, bm = idx >> 7;
    float acc = bfc[f];
    for (int ks = 0; ks < FCSPLIT; ks++) acc += g_zpart[(size_t)ks*16384 + bm*128 + f];
    g_z[idx] = acc;
}

__global__ void head_kernel(const float* __restrict__ Wout, const float* __restrict__ bout,
                            float* __restrict__ out) {
    __shared__ float zr[FCN];
    int bm = blockIdx.x, tid = threadIdx.x;
    if (tid < FCN) {
        float v = g_z[bm*FCN + tid];
        zr[tid] = v > 0.f ? v : 0.01f*v;
    }
    __syncthreads();
    if (tid < PREDN) {
        float acc = bout[tid];
        const float* wr = Wout + (size_t)tid*FCN;
        #pragma unroll 8
        for (int f = 0; f < FCN; f++) acc += zr[f]*wr[f];
        int b = bm / MMCH, m = bm % MMCH;
        out[(size_t)b*(PREDN*MMCH) + tid*MMCH + m] = acc*g_std[bm] + g_mean[bm];
    }
}

// ---------------- host ----------------
extern "C" void kernel_launch(void* const* d_in, const int* in_sizes, int n_in,
                              void* d_out, int out_size) {
    const float* x      = (const float*)d_in[0];
    const float* W_in   = (const float*)d_in[1];
    const float* b_in   = (const float*)d_in[2];
    const float* attn_w = (const float*)d_in[3];
    const float* Wq     = (const float*)d_in[4];
    const float* Wk     = (const float*)d_in[5];
    const float* Wv     = (const float*)d_in[6];
    const float* Wo     = (const float*)d_in[7];
    const float* mlp_w  = (const float*)d_in[8];
    const float* Wg     = (const float*)d_in[9];
    const float* Wu     = (const float*)d_in[10];
    const float* Wd     = (const float*)d_in[11];
    const float* fin_w  = (const float*)d_in[12];
    const float* W_fc   = (const float*)d_in[13];
    const float* b_fc   = (const float*)d_in[14];
    const float* W_out  = (const float*)d_in[15];
    const float* b_out  = (const float*)d_in[16];
    float* out = (float*)d_out;

    float *ph, *phn, *pq, *pk, *pv, *po, *pg, *pu, *pzp;
    cudaGetSymbolAddress((void**)&ph,  g_h);
    cudaGetSymbolAddress((void**)&phn, g_hn);
    cudaGetSymbolAddress((void**)&pq,  g_q);
    cudaGetSymbolAddress((void**)&pk,  g_k);
    cudaGetSymbolAddress((void**)&pv,  g_v);
    cudaGetSymbolAddress((void**)&po,  g_o);
    cudaGetSymbolAddress((void**)&pg,  g_gate);
    cudaGetSymbolAddress((void**)&pu,  g_up);
    cudaGetSymbolAddress((void**)&pzp, g_zpart);

    const int attn_smem = (64*128 + 128*65 + 64*128 + 64*65) * (int)sizeof(float);
    cudaFuncSetAttribute(attn_kernel, cudaFuncAttributeMaxDynamicSharedMemorySize, attn_smem);
    const int gemm_smem = 2 * 2 * TILEF * (int)sizeof(uint32_t);   // 73728
    cudaFuncSetAttribute(mma_gemm<0>, cudaFuncAttributeMaxDynamicSharedMemorySize, gemm_smem);
    cudaFuncSetAttribute(mma_gemm<1>, cudaFuncAttributeMaxDynamicSharedMemorySize, gemm_smem);
    cudaFuncSetAttribute(mma_gemm<2>, cudaFuncAttributeMaxDynamicSharedMemorySize, gemm_smem);

    // 1. RevIN stats
    instnorm_kernel<<<BMSEQ, 256>>>(x);
    // 2. patch embed
    patch_kernel<<<TOK, 256>>>(x, W_in, b_in);
    // 3. attn RMSNorm
    rmsnorm_kernel<<<TOK, 256>>>(ph, attn_w, phn);
    // 4-6. q/k/v projections (tf32 mma.sync)
    {
        dim3 gq(56*32, 1);
        mma_gemm<0><<<gq, 256, gemm_smem>>>(phn, DD, Wq, DD, pq, DD, nullptr,
                                            56, 32, TOK, DD/32, 0, 0, 0);
        dim3 gk(56*8, 1);
        mma_gemm<0><<<gk, 256, gemm_smem>>>(phn, DD, Wk, DD, pk, KVH*HDIM, nullptr,
                                            56, 8, TOK, DD/32, 0, 0, 0);
        mma_gemm<0><<<gk, 256, gemm_smem>>>(phn, DD, Wv, DD, pv, KVH*HDIM, nullptr,
                                            56, 8, TOK, DD/32, 0, 0, 0);
    }
    // 7. RoPE
    rope_kernel<<<TOK, 256>>>();
    // 8. attention
    {
        dim3 grid(BMSEQ, HHE);
        attn_kernel<<<grid, 256, attn_smem>>>();
    }
    // 9. output proj + residual
    {
        dim3 g(56*32, 1);
        mma_gemm<1><<<g, 256, gemm_smem>>>(po, DD, Wo, DD, ph, DD, ph,
                                           56, 32, TOK, DD/32, 0, 0, 0);
    }
    // 10. mlp RMSNorm
    rmsnorm_kernel<<<TOK, 256>>>(ph, mlp_w, phn);
    // 11. up proj, 12. gate proj with fused silu*up
    {
        dim3 g(56*112, 1);
        mma_gemm<0><<<g, 256, gemm_smem>>>(phn, DD, Wu, DD, pu, DFFN, nullptr,
                                           56, 112, TOK, DD/32, 0, 0, 0);
        mma_gemm<2><<<g, 256, gemm_smem>>>(phn, DD, Wg, DD, pg, DFFN, pu,
                                           56, 112, TOK, DD/32, 0, 0, 0);
    }
    // 13. down proj + residual
    {
        dim3 g(56*32, 1);
        mma_gemm<1><<<g, 256, gemm_smem>>>(pg, DFFN, Wd, DFFN, ph, DD, ph,
                                           56, 32, TOK, DFFN/32, 0, 0, 0);
    }
    // 14. final RMSNorm
    rmsnorm_kernel<<<TOK, 256>>>(ph, fin_w, phn);
    // 15. FC head as split-K tf32 GEMM (both A and W advance in K per split)
    {
        dim3 g(1, FCSPLIT);
        mma_gemm<0><<<g, 256, gemm_smem>>>(phn, KFC, W_fc, KFC, pzp, 128, nullptr,
                                           1, 1, 112, (KFC/FCSPLIT)/32,
                                           KFC/FCSPLIT, KFC/FCSPLIT, 128*128);
    }
    // 16. reduce + 17. head
    zreduce_kernel<<<(BMSEQ*FCN + 255)/256, 256>>>(b_fc);
    head_kernel<<<BMSEQ, 128>>>(W_out, b_out, out);
}

// round 5
// speedup vs baseline: 3.8443x; 1.2291x over previous
#include <cuda_runtime.h>
#include <math.h>
#include <stdint.h>

// ---------------- problem constants ----------------
#define BB   16
#define LL   512
#define MMCH 7
#define PP   16
#define SSTR 8
#define NPAT 64
#define DD   4096
#define HHE  32
#define KVH  8
#define HDIM 128
#define DFFN 14336
#define FCN  128
#define PREDN 96
#define BMSEQ (BB*MMCH)        // 112
#define TOK   (BMSEQ*NPAT)     // 7168
#define KFC   (NPAT*DD)        // 262144
#define FCSPLIT 64
#define EPSV 1e-5f

// ---------------- scratch ----------------
__device__ float g_mean[BMSEQ];
__device__ float g_std[BMSEQ];
__device__ float g_h [(size_t)TOK*DD];
__device__ float g_hn[(size_t)TOK*DD];
__device__ float g_q [(size_t)TOK*DD];
__device__ float g_k [(size_t)TOK*KVH*HDIM];
__device__ float g_v [(size_t)TOK*KVH*HDIM];
__device__ float g_o [(size_t)TOK*DD];
__device__ float g_gate[(size_t)TOK*DFFN];
__device__ float g_up  [(size_t)TOK*DFFN];
__device__ float g_zpart[(size_t)FCSPLIT*128*128];
__device__ float g_z[BMSEQ*FCN];
// tf32-rounded weights (1.0 GB)
#define WOFF_Q  0
#define WOFF_K  16777216
#define WOFF_V  20971520
#define WOFF_O  25165824
#define WOFF_G  41943040
#define WOFF_U  100663296
#define WOFF_D  159383552
#define WOFF_FC 218103808
#define WTF_TOTAL 251658240
__device__ float g_wtf[(size_t)WTF_TOTAL];

__device__ __forceinline__ uint32_t f2tf(float f) {
    uint32_t r;
    asm("cvt.rna.tf32.f32 %0, %1;" : "=r"(r) : "f"(f));
    return r;
}
__device__ __forceinline__ float f2tff(float f) { return __uint_as_float(f2tf(f)); }

__device__ __forceinline__ uint32_t smem_u32(const void* p) {
    uint32_t a;
    asm("{ .reg .u64 t; cvta.to.shared.u64 t, %1; cvt.u32.u64 %0, t; }" : "=r"(a) : "l"(p));
    return a;
}
__device__ __forceinline__ void mma_tf32(float c[4], const uint32_t a[4], const uint32_t b[2]) {
    asm volatile("mma.sync.aligned.m16n8k8.row.col.f32.tf32.tf32.f32 "
        "{%0,%1,%2,%3}, {%4,%5,%6,%7}, {%8,%9}, {%0,%1,%2,%3};"
        : "+f"(c[0]), "+f"(c[1]), "+f"(c[2]), "+f"(c[3])
        : "r"(a[0]), "r"(a[1]), "r"(a[2]), "r"(a[3]), "r"(b[0]), "r"(b[1]));
}
#define CP_ASYNC16(dst, src) \
    asm volatile("cp.async.cg.shared.global [%0], [%1], 16;" :: "r"(dst), "l"(src) : "memory")
#define CP_COMMIT() asm volatile("cp.async.commit_group;" ::: "memory")
#define CP_WAIT1()  asm volatile("cp.async.wait_group 1;" ::: "memory")

// ---------------- weight tf32 pre-round ----------------
__global__ void cvtw_kernel(const float4* __restrict__ src, float4* __restrict__ dst, int n4) {
    int i = blockIdx.x*256 + threadIdx.x;
    if (i < n4) {
        float4 v = src[i];
        v.x = f2tff(v.x); v.y = f2tff(v.y); v.z = f2tff(v.z); v.w = f2tff(v.w);
        dst[i] = v;
    }
}

// ---------------- mma.sync TF32 GEMM, cp.async 3-stage ----------------
// C[M,N] = A[M,K] @ W[N,K]^T (+epilogue). BM=BN=128, BK=32. Inputs pre-rounded to tf32.
// MODE: 0 plain, 1 add aux (residual), 2 silu(acc)*aux (output rounded to tf32)
#define KSTRIDE 36
#define TILEF (128*KSTRIDE)
#define STAGEB (2*TILEF*4)     // 36864 bytes

template<int MODE>
__global__ void __launch_bounds__(256, 2)
mma_gemm(const float* __restrict__ A, int lda,
         const float* __restrict__ W, int ldw,
         float* __restrict__ C, int ldc,
         const float* __restrict__ aux,
         int Mtiles, int Ntiles, int Mvalid, int kchunks,
         long ksA, long ksW, long ksC)
{
    extern __shared__ __align__(16) float smf[];
    const uint32_t sb_u = smem_u32(smf);
    const int tid = threadIdx.x;

    A += (size_t)blockIdx.y * ksA;
    W += (size_t)blockIdx.y * ksW;
    C += (size_t)blockIdx.y * ksC;

    // tile rasterization (GROUP_M=16)
    int mt, nt;
    {
        const int GM = 16;
        int perg = GM * Ntiles;
        int g = blockIdx.x / perg, rem = blockIdx.x % perg;
        int gm = Mtiles - g*GM; if (gm > GM) gm = GM;
        mt = g*GM + rem % gm;
        nt = rem / gm;
    }

    // per-thread load slots: i<4 -> A rows, i>=4 -> B rows
    const float* gp[8];
    uint32_t sob[8];
    #pragma unroll
    for (int i = 0; i < 8; i++) {
        int idx = tid + (i & 3)*256;
        int row = idx >> 3, c4 = idx & 7;
        if (i < 4) {
            int grow = mt*128 + row; if (grow >= Mvalid) grow = Mvalid-1;
            gp[i] = A + (size_t)grow*lda + c4*4;
            sob[i] = (uint32_t)(row*KSTRIDE + c4*4)*4;
        } else {
            gp[i] = W + (size_t)(nt*128 + row)*ldw + c4*4;
            sob[i] = (uint32_t)(TILEF + row*KSTRIDE + c4*4)*4;
        }
    }

    const int warp = tid >> 5, lane = tid & 31;
    const int wm = warp & 3, wn = warp >> 2;
    const int gid = lane >> 2, quad = lane & 3;

    float acc[2][8][4];
    #pragma unroll
    for (int f = 0; f < 2; f++)
        #pragma unroll
        for (int g = 0; g < 8; g++)
            #pragma unroll
            for (int j = 0; j < 4; j++) acc[f][g][j] = 0.f;

    // prologue: stages 0,1
    #pragma unroll
    for (int i = 0; i < 8; i++) CP_ASYNC16(sb_u + 0*STAGEB + sob[i], gp[i]);
    CP_COMMIT();
    #pragma unroll
    for (int i = 0; i < 8; i++) CP_ASYNC16(sb_u + 1*STAGEB + sob[i], gp[i] + 32);
    CP_COMMIT();

    int st = 0;
    for (int kc = 0; kc < kchunks; kc++) {
        CP_WAIT1();
        __syncthreads();
        // issue loads for kc+2 into stage (st+2)%3
        if (kc + 2 < kchunks) {
            int s2 = st + 2; if (s2 >= 3) s2 -= 3;
            uint32_t base = sb_u + (uint32_t)s2*STAGEB;
            const long koff = (long)(kc+2)*32;
            #pragma unroll
            for (int i = 0; i < 8; i++) CP_ASYNC16(base + sob[i], gp[i] + koff);
        }
        CP_COMMIT();
        // compute on stage st
        const uint32_t* sA = (const uint32_t*)(smf + st*(2*TILEF));
        const uint32_t* sB = sA + TILEF;
        #pragma unroll
        for (int ks = 0; ks < 4; ks++) {
            const int kb = ks*8;
            uint32_t a[2][4];
            #pragma unroll
            for (int f = 0; f < 2; f++) {
                int r0 = wm*32 + f*16 + gid;
                a[f][0] = sA[r0*KSTRIDE + kb + quad];
                a[f][1] = sA[(r0+8)*KSTRIDE + kb + quad];
                a[f][2] = sA[r0*KSTRIDE + kb + quad + 4];
                a[f][3] = sA[(r0+8)*KSTRIDE + kb + quad + 4];
            }
            uint32_t b[8][2];
            #pragma unroll
            for (int g = 0; g < 8; g++) {
                int nr = wn*64 + g*8 + gid;
                b[g][0] = sB[nr*KSTRIDE + kb + quad];
                b[g][1] = sB[nr*KSTRIDE + kb + quad + 4];
            }
            #pragma unroll
            for (int f = 0; f < 2; f++)
                #pragma unroll
                for (int g = 0; g < 8; g++)
                    mma_tf32(acc[f][g], a[f], b[g]);
        }
        st = st + 1; if (st == 3) st = 0;
    }

    // epilogue
    #pragma unroll
    for (int f = 0; f < 2; f++) {
        int r0 = mt*128 + wm*32 + f*16 + gid;
        #pragma unroll
        for (int g = 0; g < 8; g++) {
            int col = nt*128 + wn*64 + g*8 + 2*quad;
            #pragma unroll
            for (int half = 0; half < 2; half++) {
                int row = r0 + half*8;
                if (row >= Mvalid) continue;
                float v0 = acc[f][g][half*2 + 0];
                float v1 = acc[f][g][half*2 + 1];
                size_t off = (size_t)row*ldc + col;
                if (MODE == 1) {
                    v0 += aux[off]; v1 += aux[off+1];
                } else if (MODE == 2) {
                    v0 = f2tff(v0 / (1.f + __expf(-v0)) * aux[off]);
                    v1 = f2tff(v1 / (1.f + __expf(-v1)) * aux[off+1]);
                }
                float2 o; o.x = v0; o.y = v1;
                *(float2*)(C + off) = o;
            }
        }
    }
}

// ---------------- instance norm ----------------
__global__ void instnorm_kernel(const float* __restrict__ x) {
    __shared__ float r1[256], r2[256];
    int bm = blockIdx.x, b = bm / MMCH, m = bm % MMCH, tid = threadIdx.x;
    float s = 0.f, s2 = 0.f;
    for (int l = tid; l < LL; l += 256) {
        float v = x[((size_t)b*LL + l)*MMCH + m];
        s += v; s2 += v*v;
    }
    r1[tid] = s; r2[tid] = s2; __syncthreads();
    for (int o = 128; o; o >>= 1) {
        if (tid < o) { r1[tid] += r1[tid+o]; r2[tid] += r2[tid+o]; }
        __syncthreads();
    }
    if (tid == 0) {
        float mu  = r1[0] / (float)LL;
        float var = r2[0] / (float)LL - mu*mu;
        g_mean[bm] = mu;
        g_std[bm]  = sqrtf(var + EPSV);
    }
}

// ---------------- patch embed ----------------
__global__ void patch_kernel(const float* __restrict__ x, const float* __restrict__ Win,
                             const float* __restrict__ bin) {
    int bmn = blockIdx.x;
    int bm = bmn >> 6, n = bmn & 63;
    int b = bm / MMCH, m = bm % MMCH;
    __shared__ float patch[PP];
    int tid = threadIdx.x;
    if (tid < PP) {
        int l = n*SSTR + tid;
        if (l > LL-1) l = LL-1;
        patch[tid] = (x[((size_t)b*LL + l)*MMCH + m] - g_mean[bm]) / g_std[bm];
    }
    __syncthreads();
    for (int d = tid; d < DD; d += 256) {
        float acc = bin[d];
        const float* wr = Win + (size_t)d*PP;
        #pragma unroll
        for (int p = 0; p < PP; p++) acc += patch[p]*wr[p];
        g_h[(size_t)bmn*DD + d] = acc;
    }
}

// ---------------- RMSNorm (output rounded to tf32: GEMM A input) ----------------
__global__ void rmsnorm_kernel(const float* __restrict__ in, const float* __restrict__ w,
                               float* __restrict__ out) {
    __shared__ float red[256];
    int row = blockIdx.x, tid = threadIdx.x;
    const float* r = in + (size_t)row*DD;
    float s = 0.f;
    for (int i = tid; i < DD; i += 256) { float v = r[i]; s += v*v; }
    red[tid] = s; __syncthreads();
    for (int o = 128; o; o >>= 1) { if (tid < o) red[tid] += red[tid+o]; __syncthreads(); }
    float scale = rsqrtf(red[0]/(float)DD + EPSV);
    float* outr = out + (size_t)row*DD;
    for (int i = tid; i < DD; i += 256) outr[i] = f2tff(r[i]*scale*w[i]);
}

// ---------------- RoPE ----------------
__global__ void rope_kernel() {
    int row = blockIdx.x;
    int n = row & 63;
    float* qrow = g_q + (size_t)row*DD;
    float* krow = g_k + (size_t)row*(KVH*HDIM);
    int tid = threadIdx.x;
    const int qpairs = HHE*64;
    const int kpairs = KVH*64;
    for (int i = tid; i < qpairs + kpairs; i += 256) {
        float* base; int hh, d;
        if (i < qpairs) { base = qrow; hh = i >> 6; d = i & 63; }
        else            { int j = i - qpairs; base = krow; hh = j >> 6; d = j & 63; }
        float f = powf(500000.0f, -(float)(2*d) / 128.0f);
        float a = (float)n * f;
        float c = cosf(a), s = sinf(a);
        float t0 = base[hh*HDIM + d];
        float t1 = base[hh*HDIM + d + 64];
        base[hh*HDIM + d]      = t0*c - t1*s;
        base[hh*HDIM + d + 64] = t1*c + t0*s;
    }
}

// ---------------- attention (output rounded: Wo GEMM A input) ----------------
__global__ void attn_kernel() {
    extern __shared__ float sm[];
    float* Qs = sm;
    float* Ks = Qs + 64*128;
    float* Vs = Ks + 128*65;
    float* Ss = Vs + 64*128;
    int bm = blockIdx.x, h = blockIdx.y, kvh = h >> 2;
    int tid = threadIdx.x;
    for (int i = tid; i < 64*128; i += 256) {
        int n = i >> 7, d = i & 127;
        size_t tok = (size_t)(bm*64 + n);
        Qs[i] = g_q[tok*DD + h*HDIM + d];
        Ks[d*65 + n] = g_k[tok*(KVH*HDIM) + kvh*HDIM + d];
        Vs[i] = g_v[tok*(KVH*HDIM) + kvh*HDIM + d];
    }
    __syncthreads();
    const float scale = 0.08838834764831845f;
    for (int i = tid; i < 64*64; i += 256) {
        int qi = i >> 6, ki = i & 63;
        float acc;
        if (ki <= qi) {
            acc = 0.f;
            #pragma unroll 8
            for (int d = 0; d < 128; d++) acc += Qs[qi*128 + d]*Ks[d*65 + ki];
            acc *= scale;
        } else acc = -1e9f;
        Ss[qi*65 + ki] = acc;
    }
    __syncthreads();
    if (tid < 64) {
        float mx = -1e30f;
        for (int k = 0; k < 64; k++) mx = fmaxf(mx, Ss[tid*65 + k]);
        float sum = 0.f;
        for (int k = 0; k < 64; k++) { float e = expf(Ss[tid*65 + k] - mx); Ss[tid*65 + k] = e; sum += e; }
        float inv = 1.f / sum;
        for (int k = 0; k < 64; k++) Ss[tid*65 + k] *= inv;
    }
    __syncthreads();
    for (int i = tid; i < 64*128; i += 256) {
        int qi = i >> 7, d = i & 127;
        float acc = 0.f;
        #pragma unroll 8
        for (int k = 0; k < 64; k++) acc += Ss[qi*65 + k]*Vs[k*128 + d];
        g_o[(size_t)(bm*64 + qi)*DD + h*HDIM + d] = f2tff(acc);
    }
}

// ---------------- FC reduce + head ----------------
__global__ void zreduce_kernel(const float* __restrict__ bfc) {
    int idx = blockIdx.x*256 + threadIdx.x;
    if (idx >= BMSEQ*FCN) return;
    int f = idx & 127, bm = idx >> 7;
    float acc = bfc[f];
    for (int ks = 0; ks < FCSPLIT; ks++) acc += g_zpart[(size_t)ks*16384 + bm*128 + f];
    g_z[idx] = acc;
}

__global__ void head_kernel(const float* __restrict__ Wout, const float* __restrict__ bout,
                            float* __restrict__ out) {
    __shared__ float zr[FCN];
    int bm = blockIdx.x, tid = threadIdx.x;
    if (tid < FCN) {
        float v = g_z[bm*FCN + tid];
        zr[tid] = v > 0.f ? v : 0.01f*v;
    }
    __syncthreads();
    if (tid < PREDN) {
        float acc = bout[tid];
        const float* wr = Wout + (size_t)tid*FCN;
        #pragma unroll 8
        for (int f = 0; f < FCN; f++) acc += zr[f]*wr[f];
        int b = bm / MMCH, m = bm % MMCH;
        out[(size_t)b*(PREDN*MMCH) + tid*MMCH + m] = acc*g_std[bm] + g_mean[bm];
    }
}

// ---------------- host ----------------
extern "C" void kernel_launch(void* const* d_in, const int* in_sizes, int n_in,
                              void* d_out, int out_size) {
    const float* x      = (const float*)d_in[0];
    const float* W_in   = (const float*)d_in[1];
    const float* b_in   = (const float*)d_in[2];
    const float* attn_w = (const float*)d_in[3];
    const float* Wq     = (const float*)d_in[4];
    const float* Wk     = (const float*)d_in[5];
    const float* Wv     = (const float*)d_in[6];
    const float* Wo     = (const float*)d_in[7];
    const float* mlp_w  = (const float*)d_in[8];
    const float* Wg     = (const float*)d_in[9];
    const float* Wu     = (const float*)d_in[10];
    const float* Wd     = (const float*)d_in[11];
    const float* fin_w  = (const float*)d_in[12];
    const float* W_fc   = (const float*)d_in[13];
    const float* b_fc   = (const float*)d_in[14];
    const float* W_out  = (const float*)d_in[15];
    const float* b_out  = (const float*)d_in[16];
    float* out = (float*)d_out;

    float *ph, *phn, *pq, *pk, *pv, *po, *pg, *pu, *pzp, *pw;
    cudaGetSymbolAddress((void**)&ph,  g_h);
    cudaGetSymbolAddress((void**)&phn, g_hn);
    cudaGetSymbolAddress((void**)&pq,  g_q);
    cudaGetSymbolAddress((void**)&pk,  g_k);
    cudaGetSymbolAddress((void**)&pv,  g_v);
    cudaGetSymbolAddress((void**)&po,  g_o);
    cudaGetSymbolAddress((void**)&pg,  g_gate);
    cudaGetSymbolAddress((void**)&pu,  g_up);
    cudaGetSymbolAddress((void**)&pzp, g_zpart);
    cudaGetSymbolAddress((void**)&pw,  g_wtf);

    const int attn_smem = (64*128 + 128*65 + 64*128 + 64*65) * (int)sizeof(float);
    cudaFuncSetAttribute(attn_kernel, cudaFuncAttributeMaxDynamicSharedMemorySize, attn_smem);
    const int gemm_smem = 3 * STAGEB;   // 110592
    cudaFuncSetAttribute(mma_gemm<0>, cudaFuncAttributeMaxDynamicSharedMemorySize, gemm_smem);
    cudaFuncSetAttribute(mma_gemm<1>, cudaFuncAttributeMaxDynamicSharedMemorySize, gemm_smem);
    cudaFuncSetAttribute(mma_gemm<2>, cudaFuncAttributeMaxDynamicSharedMemorySize, gemm_smem);

    // 0. pre-round all GEMM weights to tf32
    {
        struct { const float* src; long off; int cnt; } ws[8] = {
            {Wq, WOFF_Q, 16777216}, {Wk, WOFF_K, 4194304}, {Wv, WOFF_V, 4194304},
            {Wo, WOFF_O, 16777216}, {Wg, WOFF_G, 58720256}, {Wu, WOFF_U, 58720256},
            {Wd, WOFF_D, 58720256}, {W_fc, WOFF_FC, 33554432}
        };
        for (int i = 0; i < 8; i++) {
            int n4 = ws[i].cnt / 4;
            cvtw_kernel<<<(n4 + 255)/256, 256>>>((const float4*)ws[i].src,
                                                 (float4*)(pw + ws[i].off), n4);
        }
    }
    const float* tWq = pw + WOFF_Q;  const float* tWk = pw + WOFF_K;
    const float* tWv = pw + WOFF_V;  const float* tWo = pw + WOFF_O;
    const float* tWg = pw + WOFF_G;  const float* tWu = pw + WOFF_U;
    const float* tWd = pw + WOFF_D;  const float* tWfc = pw + WOFF_FC;

    // 1. RevIN stats
    instnorm_kernel<<<BMSEQ, 256>>>(x);
    // 2. patch embed
    patch_kernel<<<TOK, 256>>>(x, W_in, b_in);
    // 3. attn RMSNorm (tf32-rounded out)
    rmsnorm_kernel<<<TOK, 256>>>(ph, attn_w, phn);
    // 4-6. q/k/v projections
    {
        dim3 gq(56*32, 1);
        mma_gemm<0><<<gq, 256, gemm_smem>>>(phn, DD, tWq, DD, pq, DD, nullptr,
                                            56, 32, TOK, DD/32, 0, 0, 0);
        dim3 gk(56*8, 1);
        mma_gemm<0><<<gk, 256, gemm_smem>>>(phn, DD, tWk, DD, pk, KVH*HDIM, nullptr,
                                            56, 8, TOK, DD/32, 0, 0, 0);
        mma_gemm<0><<<gk, 256, gemm_smem>>>(phn, DD, tWv, DD, pv, KVH*HDIM, nullptr,
                                            56, 8, TOK, DD/32, 0, 0, 0);
    }
    // 7. RoPE
    rope_kernel<<<TOK, 256>>>();
    // 8. attention
    {
        dim3 grid(BMSEQ, HHE);
        attn_kernel<<<grid, 256, attn_smem>>>();
    }
    // 9. output proj + residual
    {
        dim3 g(56*32, 1);
        mma_gemm<1><<<g, 256, gemm_smem>>>(po, DD, tWo, DD, ph, DD, ph,
                                           56, 32, TOK, DD/32, 0, 0, 0);
    }
    // 10. mlp RMSNorm
    rmsnorm_kernel<<<TOK, 256>>>(ph, mlp_w, phn);
    // 11. up proj, 12. gate proj fused silu*up (output tf32-rounded)
    {
        dim3 g(56*112, 1);
        mma_gemm<0><<<g, 256, gemm_smem>>>(phn, DD, tWu, DD, pu, DFFN, nullptr,
                                           56, 112, TOK, DD/32, 0, 0, 0);
        mma_gemm<2><<<g, 256, gemm_smem>>>(phn, DD, tWg, DD, pg, DFFN, pu,
                                           56, 112, TOK, DD/32, 0, 0, 0);
    }
    // 13. down proj + residual
    {
        dim3 g(56*32, 1);
        mma_gemm<1><<<g, 256, gemm_smem>>>(pg, DFFN, tWd, DFFN, ph, DD, ph,
                                           56, 32, TOK, DFFN/32, 0, 0, 0);
    }
    // 14. final RMSNorm
    rmsnorm_kernel<<<TOK, 256>>>(ph, fin_w, phn);
    // 15. FC head: split-K tf32 GEMM
    {
        dim3 g(1, FCSPLIT);
        mma_gemm<0><<<g, 256, gemm_smem>>>(phn, KFC, tWfc, KFC, pzp, 128, nullptr,
                                           1, 1, 112, (KFC/FCSPLIT)/32,
                                           KFC/FCSPLIT, KFC/FCSPLIT, 128*128);
    }
    // 16. reduce + 17. head
    zreduce_kernel<<<(BMSEQ*FCN + 255)/256, 256>>>(b_fc);
    head_kernel<<<BMSEQ, 128>>>(W_out, b_out, out);
}